// round 15
// baseline (speedup 1.0000x reference)
#include <cuda_runtime.h>
#include <cuda_fp16.h>
#include <cstdint>
#include <cstddef>

#define NN 2048
#define NROWS 16384   // B * N

// ---------------- device scratch ----------------
__device__ __align__(128) float  g_dinv[NROWS];            // rsqrt(rowsum(A)+1)
__device__ __align__(128) __half g_Ah[(size_t)NROWS * NN]; // fp16 copy of A (64MB)
__device__ __align__(128) float  g_M1[NROWS * 64];         // d_j*(X@W1), f32 row-major
__device__ __align__(128) __half g_M1T[8 * 64 * NN];       // fp16 n-major M1 [b][64][2048]
__device__ __align__(128) float  g_Pp[NROWS * 16];         // d_j*(h_drop@W2), f32 row-major
__device__ __align__(128) __half g_PpT[8 * 16 * NN];       // fp16 n-major Pp [b][16][2048]

// ---------------- helpers ----------------
__device__ __forceinline__ uint32_t smem_u32(const void* p) {
    uint32_t a;
    asm("{ .reg .u64 t; cvta.to.shared.u64 t, %1; cvt.u32.u64 %0, t; }" : "=r"(a) : "l"(p));
    return a;
}
__device__ __forceinline__ void cp16(uint32_t dst, const void* src) {
    asm volatile("cp.async.cg.shared.global [%0], [%1], 16;" :: "r"(dst), "l"(src) : "memory");
}
__device__ __forceinline__ void mma_f16(float* c, const uint32_t* a, const uint32_t* b) {
    asm volatile("mma.sync.aligned.m16n8k16.row.col.f32.f16.f16.f32 "
                 "{%0,%1,%2,%3}, {%4,%5,%6,%7}, {%8,%9}, {%0,%1,%2,%3};"
                 : "+f"(c[0]), "+f"(c[1]), "+f"(c[2]), "+f"(c[3])
                 : "r"(a[0]), "r"(a[1]), "r"(a[2]), "r"(a[3]), "r"(b[0]), "r"(b[1]));
}

// ---------------- exact JAX threefry2x32 (partitionable), key = (0, 42) ----------------
__device__ __forceinline__ unsigned tf_rotl(unsigned x, int r) { return (x << r) | (x >> (32 - r)); }
__device__ __forceinline__ void threefry(unsigned x0, unsigned x1, unsigned &o0, unsigned &o1) {
    const unsigned k0 = 0u, k1 = 42u;
    const unsigned k2 = 0x1BD11BDAu ^ k0 ^ k1;
    x0 += k0; x1 += k1;
#define RND(r) { x0 += x1; x1 = tf_rotl(x1, (r)); x1 ^= x0; }
    RND(13) RND(15) RND(26) RND(6)   x0 += k1; x1 += k2 + 1u;
    RND(17) RND(29) RND(16) RND(24)  x0 += k2; x1 += k0 + 2u;
    RND(13) RND(15) RND(26) RND(6)   x0 += k0; x1 += k1 + 3u;
    RND(17) RND(29) RND(16) RND(24)  x0 += k1; x1 += k2 + 4u;
    RND(13) RND(15) RND(26) RND(6)   x0 += k2; x1 += k0 + 5u;
#undef RND
    o0 = x0; o1 = x1;
}

// ---------------- K1: d = rsqrt(rowsum+1) AND g_Ah = fp16(A) ----------------
__global__ __launch_bounds__(256) void k1_prep(const float* __restrict__ A) {
    int row  = blockIdx.x * 8 + (threadIdx.x >> 5);
    int lane = threadIdx.x & 31;
    const float4* p = reinterpret_cast<const float4*>(A + (size_t)row * NN);
    uint2* q = reinterpret_cast<uint2*>(g_Ah + (size_t)row * NN);
    float s = 0.f;
#pragma unroll
    for (int it = 0; it < 16; ++it) {
        float4 v = p[it * 32 + lane];
        s += (v.x + v.y) + (v.z + v.w);
        __half2 h0 = __floats2half2_rn(v.x, v.y);
        __half2 h1 = __floats2half2_rn(v.z, v.w);
        uint2 w;
        w.x = *reinterpret_cast<uint32_t*>(&h0);
        w.y = *reinterpret_cast<uint32_t*>(&h1);
        q[it * 32 + lane] = w;
    }
#pragma unroll
    for (int o = 16; o; o >>= 1) s += __shfl_xor_sync(0xffffffffu, s, o);
    if (lane == 0) g_dinv[row] = rsqrtf(s + 1.0f);
}

// ---------------- K2: M1 = d*(X@W1) -> f32 row-major + fp16 n-major ----------------
__global__ __launch_bounds__(256) void k2_xw(const float* __restrict__ X,
                                             const float* __restrict__ W1) {
    __shared__ __align__(16) float Ws[64][64];
    __shared__ float Xs[16][68];
    int tid  = threadIdx.x;
    int row0 = blockIdx.x * 16;
#pragma unroll
    for (int s = 0; s < 4; ++s) {
        int slot = tid + s * 256;
        *reinterpret_cast<float4*>(&Ws[0][0] + (size_t)slot * 4) =
            reinterpret_cast<const float4*>(W1)[slot];
    }
    {
        int r = tid >> 4, cq = tid & 15;
        float4 v = reinterpret_cast<const float4*>(X + (size_t)(row0 + r) * 64)[cq];
        Xs[r][cq * 4 + 0] = v.x; Xs[r][cq * 4 + 1] = v.y;
        Xs[r][cq * 4 + 2] = v.z; Xs[r][cq * 4 + 3] = v.w;
    }
    __syncthreads();
    int r = tid >> 4, cx = tid & 15;
    float4 acc = make_float4(0.f, 0.f, 0.f, 0.f);
#pragma unroll
    for (int k = 0; k < 64; ++k) {
        float x  = Xs[r][k];
        float4 w = *reinterpret_cast<const float4*>(&Ws[k][cx * 4]);
        acc.x = fmaf(x, w.x, acc.x);
        acc.y = fmaf(x, w.y, acc.y);
        acc.z = fmaf(x, w.z, acc.z);
        acc.w = fmaf(x, w.w, acc.w);
    }
    int grow = row0 + r;
    float d  = g_dinv[grow];
    acc.x *= d; acc.y *= d; acc.z *= d; acc.w *= d;
    reinterpret_cast<float4*>(g_M1 + (size_t)grow * 64)[cx] = acc;
    int bT = grow >> 11, rl = grow & 2047;
    g_M1T[((size_t)bT * 64 + cx * 4 + 0) * NN + rl] = __float2half_rn(acc.x);
    g_M1T[((size_t)bT * 64 + cx * 4 + 1) * NN + rl] = __float2half_rn(acc.y);
    g_M1T[((size_t)bT * 64 + cx * 4 + 2) * NN + rl] = __float2half_rn(acc.z);
    g_M1T[((size_t)bT * 64 + cx * 4 + 3) * NN + rl] = __float2half_rn(acc.w);
}

// ================= GEMM1: T1 = A@M1 + fused act/dropout/W2 epilogue =================
// 128-row tile, 8 warps, each warp owns 16 rows with a PRIVATE 4-stage cp.async
// pipeline (chunk = 64 halves). B (64 x 2048 fp16) is macro-double-buffered:
// 4 macros of 64 x 512; block barrier only at macro boundaries.
__global__ __launch_bounds__(256) void gemm1(const float* __restrict__ b1g,
                                             const float* __restrict__ W2g) {
    constexpr int ASTR = 72;                 // halves (64 + 8 pad)
    constexpr int AWSTG = 16 * ASTR;         // 1152 halves per warp-stage
    constexpr int ATOT = 4 * 8 * AWSTG;      // 36864 halves
    constexpr int BSTR = 520;                // halves (512 + 8 pad)
    constexpr int BBUF = 64 * BSTR;          // 33280 halves per macro buffer
    extern __shared__ __align__(16) __half smemh[];
    __half* Bbase = smemh + ATOT;

    const int tid = threadIdx.x, wid = tid >> 5, lane = tid & 31;
    const int bb = blockIdx.y, row0 = blockIdx.x << 7;
    const __half* Ab = g_Ah + ((size_t)(bb * NN + row0 + wid * 16)) * NN;
    const __half* BT = g_M1T + (size_t)bb * 64 * NN;
    const uint32_t sb = smem_u32(smemh);

    float acc[8][4];
#pragma unroll
    for (int j = 0; j < 8; ++j)
#pragma unroll
        for (int q = 0; q < 4; ++q) acc[j][q] = 0.f;

    // per-warp A chunk load: 16 rows x 128B; lane -> (row = lane>>1, 4 cp16)
    auto loadA = [&](int c, int s) {
        uint32_t ab = sb + (uint32_t)((s * 8 + wid) * AWSTG * 2);
        int r = lane >> 1, q0 = (lane & 1) * 4;
#pragma unroll
        for (int j = 0; j < 4; ++j)
            cp16(ab + (uint32_t)(r * ASTR * 2 + (q0 + j) * 16),
                 Ab + (size_t)r * NN + c * 64 + (q0 + j) * 8);
        asm volatile("cp.async.commit_group;" ::: "memory");
    };
    // cooperative B macro load (no commit; folds into next A group)
    auto loadB = [&](int m, int q) {
        uint32_t bbs = sb + (uint32_t)((ATOT + q * BBUF) * 2);
#pragma unroll
        for (int t = 0; t < 16; ++t) {
            int idx = tid + t * 256;
            int n = idx >> 6, qq = idx & 63;
            cp16(bbs + (uint32_t)(n * BSTR * 2 + qq * 16),
                 BT + (size_t)n * NN + m * 512 + qq * 8);
        }
    };

    // prologue: B macro 0 (own group) + A chunks 0..2
    loadB(0, 0);
    asm volatile("cp.async.commit_group;" ::: "memory");
    loadA(0, 0); loadA(1, 1); loadA(2, 2);
    asm volatile("cp.async.wait_group 3;" ::: "memory");   // B macro 0 resident
    __syncthreads();

    const int arow = lane >> 2, acol = lane & 3;
#pragma unroll 1
    for (int i = 0; i < 32; ++i) {
        if ((i & 7) == 0 && i < 24) loadB(i / 8 + 1, (i / 8 + 1) & 1);  // folds into next commit
        asm volatile("cp.async.wait_group 2;" ::: "memory");            // warp's chunk i resident
        if (i < 29) loadA(i + 3, (i + 3) & 3);
        else        asm volatile("cp.async.commit_group;" ::: "memory");
        const __half* As = smemh + (size_t)((i & 3) * 8 + wid) * AWSTG;
        const __half* Bs = Bbase + (size_t)((i >> 3) & 1) * BBUF;
#pragma unroll
        for (int ks = 0; ks < 4; ++ks) {
            int kh = ks * 16 + 2 * acol;              // within chunk
            int km = (i & 7) * 64 + kh;               // within macro
            uint32_t af[4];
            af[0] = *reinterpret_cast<const uint32_t*>(&As[arow * ASTR + kh]);
            af[1] = *reinterpret_cast<const uint32_t*>(&As[(arow + 8) * ASTR + kh]);
            af[2] = *reinterpret_cast<const uint32_t*>(&As[arow * ASTR + kh + 8]);
            af[3] = *reinterpret_cast<const uint32_t*>(&As[(arow + 8) * ASTR + kh + 8]);
#pragma unroll
            for (int ni = 0; ni < 8; ++ni) {
                int n = ni * 8 + arow;
                uint32_t bf[2];
                bf[0] = *reinterpret_cast<const uint32_t*>(&Bs[n * BSTR + km]);
                bf[1] = *reinterpret_cast<const uint32_t*>(&Bs[n * BSTR + km + 8]);
                mma_f16(acc[ni], af, bf);
            }
        }
        if ((i & 7) == 7) __syncthreads();            // macro boundary (4 total)
    }

    // ---- fused epilogue: relu(d*(acc+M1)+b1) -> threefry dropout -> Pp = d*(h@W2) ----
    constexpr int HSTR = 66;
    float* hs  = reinterpret_cast<float*>(smemh);     // [128][66]
    float* W2s = hs + 128 * HSTR;                     // [64][16]
    __syncthreads();                                  // all reads of pipeline smem done
    reinterpret_cast<float4*>(W2s)[tid] = reinterpret_cast<const float4*>(W2g)[tid];
#pragma unroll
    for (int h = 0; h < 2; ++h) {
        int r = wid * 16 + arow + h * 8;
        size_t grow = (size_t)bb * NN + row0 + r;
        float dv = g_dinv[grow];
#pragma unroll
        for (int ni = 0; ni < 8; ++ni) {
            int c = ni * 8 + acol * 2;
#pragma unroll
            for (int e = 0; e < 2; ++e) {
                float val = acc[ni][h * 2 + e];
                float pre = dv * (val + g_M1[grow * 64 + c + e]) + b1g[c + e];
                float hh  = fmaxf(pre, 0.0f);
                unsigned idx = ((unsigned)grow << 6) + (unsigned)(c + e);
                unsigned o0, o1;
                threefry(0u, idx, o0, o1);
                hs[r * HSTR + c + e] = ((o0 ^ o1) & 0x80000000u) ? 0.0f : hh + hh;
            }
        }
    }
    __syncthreads();
    int r2 = tid >> 1, cg = (tid & 1) * 8;
    float a8[8] = {0.f, 0.f, 0.f, 0.f, 0.f, 0.f, 0.f, 0.f};
#pragma unroll
    for (int k = 0; k < 64; ++k) {
        float hv = hs[r2 * HSTR + k];
        float4 w0 = *reinterpret_cast<const float4*>(&W2s[k * 16 + cg]);
        float4 w1 = *reinterpret_cast<const float4*>(&W2s[k * 16 + cg + 4]);
        a8[0] = fmaf(hv, w0.x, a8[0]); a8[1] = fmaf(hv, w0.y, a8[1]);
        a8[2] = fmaf(hv, w0.z, a8[2]); a8[3] = fmaf(hv, w0.w, a8[3]);
        a8[4] = fmaf(hv, w1.x, a8[4]); a8[5] = fmaf(hv, w1.y, a8[5]);
        a8[6] = fmaf(hv, w1.z, a8[6]); a8[7] = fmaf(hv, w1.w, a8[7]);
    }
    size_t grow2 = (size_t)bb * NN + row0 + r2;
    float dv2 = g_dinv[grow2];
#pragma unroll
    for (int j = 0; j < 8; ++j) a8[j] *= dv2;
    *reinterpret_cast<float4*>(&g_Pp[grow2 * 16 + cg])     = make_float4(a8[0], a8[1], a8[2], a8[3]);
    *reinterpret_cast<float4*>(&g_Pp[grow2 * 16 + cg + 4]) = make_float4(a8[4], a8[5], a8[6], a8[7]);
    int rl = (int)(grow2 & 2047);
#pragma unroll
    for (int j = 0; j < 8; ++j)
        g_PpT[((size_t)bb * 16 + cg + j) * NN + rl] = __float2half_rn(a8[j]);
}

// ================= GEMM2: out = d*(A@Pp + Pp) + b2 =================
// 128-row tile, 8 warps; warp-private 4-stage A pipeline (chunk = 128 halves);
// B (16 x 2048 fp16 = 64KB + pad) fully resident; NO barrier in main loop.
__global__ __launch_bounds__(256) void gemm2(const float* __restrict__ b2,
                                             float* __restrict__ out) {
    constexpr int ASTR = 136;                // halves (128 + 8 pad)
    constexpr int AWSTG = 16 * ASTR;         // 2176 halves per warp-stage
    constexpr int ATOT = 4 * 8 * AWSTG;      // 69632 halves
    constexpr int BSTR = 2056;               // halves (2048 + 8 pad)
    extern __shared__ __align__(16) __half smemh[];
    __half* Bs = smemh + ATOT;

    const int tid = threadIdx.x, wid = tid >> 5, lane = tid & 31;
    const int bb = blockIdx.y, row0 = blockIdx.x << 7;
    const __half* Ab = g_Ah + ((size_t)(bb * NN + row0 + wid * 16)) * NN;
    const __half* BT = g_PpT + (size_t)bb * 16 * NN;
    const uint32_t sb = smem_u32(smemh);

    float acc[2][4];
#pragma unroll
    for (int j = 0; j < 2; ++j)
#pragma unroll
        for (int q = 0; q < 4; ++q) acc[j][q] = 0.f;

    auto loadA = [&](int c, int s) {
        uint32_t ab = sb + (uint32_t)((s * 8 + wid) * AWSTG * 2);
        int r = lane >> 1, q0 = (lane & 1) * 8;
#pragma unroll
        for (int j = 0; j < 8; ++j)
            cp16(ab + (uint32_t)(r * ASTR * 2 + (q0 + j) * 16),
                 Ab + (size_t)r * NN + c * 128 + (q0 + j) * 8);
        asm volatile("cp.async.commit_group;" ::: "memory");
    };

    // prologue: full B (own group) + A chunks 0..2
    {
        uint32_t bbs = sb + (uint32_t)(ATOT * 2);
#pragma unroll
        for (int t = 0; t < 16; ++t) {
            int idx = tid + t * 256;
            int n = idx >> 8, q = idx & 255;
            cp16(bbs + (uint32_t)(n * BSTR * 2 + q * 16),
                 BT + (size_t)n * NN + q * 8);
        }
        asm volatile("cp.async.commit_group;" ::: "memory");
    }
    loadA(0, 0); loadA(1, 1); loadA(2, 2);
    asm volatile("cp.async.wait_group 3;" ::: "memory");   // B resident
    __syncthreads();

    const int arow = lane >> 2, acol = lane & 3;
#pragma unroll 1
    for (int i = 0; i < 16; ++i) {
        asm volatile("cp.async.wait_group 2;" ::: "memory");   // warp's chunk i resident
        if (i < 13) loadA(i + 3, (i + 3) & 3);
        else        asm volatile("cp.async.commit_group;" ::: "memory");
        const __half* As = smemh + (size_t)((i & 3) * 8 + wid) * AWSTG;
#pragma unroll
        for (int ks = 0; ks < 8; ++ks) {
            int kh = ks * 16 + 2 * acol;              // within chunk
            int kg = i * 128 + kh;                    // global k
            uint32_t af[4];
            af[0] = *reinterpret_cast<const uint32_t*>(&As[arow * ASTR + kh]);
            af[1] = *reinterpret_cast<const uint32_t*>(&As[(arow + 8) * ASTR + kh]);
            af[2] = *reinterpret_cast<const uint32_t*>(&As[arow * ASTR + kh + 8]);
            af[3] = *reinterpret_cast<const uint32_t*>(&As[(arow + 8) * ASTR + kh + 8]);
#pragma unroll
            for (int ni = 0; ni < 2; ++ni) {
                int n = ni * 8 + arow;
                uint32_t bf[2];
                bf[0] = *reinterpret_cast<const uint32_t*>(&Bs[n * BSTR + kg]);
                bf[1] = *reinterpret_cast<const uint32_t*>(&Bs[n * BSTR + kg + 8]);
                mma_f16(acc[ni], af, bf);
            }
        }
    }

    // ---- epilogue: out = d*(acc + Pp) + b2 ----
#pragma unroll
    for (int ni = 0; ni < 2; ++ni) {
#pragma unroll
        for (int h = 0; h < 2; ++h) {
            int r = wid * 16 + arow + h * 8;
            int c = ni * 8 + acol * 2;
            float v0 = acc[ni][h * 2 + 0];
            float v1 = acc[ni][h * 2 + 1];
            size_t grow = (size_t)bb * NN + row0 + r;
            float dv = g_dinv[grow];
            float p0 = g_Pp[grow * 16 + c];
            float p1 = g_Pp[grow * 16 + c + 1];
            float2 o;
            o.x = dv * (v0 + p0) + b2[c];
            o.y = dv * (v1 + p1) + b2[c + 1];
            *reinterpret_cast<float2*>(out + grow * 16 + c) = o;
        }
    }
}

// ---------------- launch ----------------
extern "C" void kernel_launch(void* const* d_in, const int* in_sizes, int n_in,
                              void* d_out, int out_size) {
    const float* X  = (const float*)d_in[0];
    const float* A  = (const float*)d_in[1];
    const float* W1 = (const float*)d_in[2];
    const float* b1 = (const float*)d_in[3];
    const float* W2 = (const float*)d_in[4];
    const float* b2 = (const float*)d_in[5];
    float* out = (float*)d_out;

    const int SM1 = (36864 + 2 * 64 * 520) * 2;   // 206848 B
    const int SM2 = (69632 + 16 * 2056) * 2;      // 205056 B
    cudaFuncSetAttribute((const void*)gemm1, cudaFuncAttributeMaxDynamicSharedMemorySize, SM1);
    cudaFuncSetAttribute((const void*)gemm2, cudaFuncAttributeMaxDynamicSharedMemorySize, SM2);

    k1_prep<<<2048, 256>>>(A);
    k2_xw<<<1024, 256>>>(X, W1);
    gemm1<<<dim3(16, 8), 256, SM1>>>(b1, W2);
    gemm2<<<dim3(16, 8), 256, SM2>>>(b2, out);
}